// round 13
// baseline (speedup 1.0000x reference)
#include <cuda_runtime.h>
#include <math.h>

#define B_  8
#define C_  12
#define S_  784
#define NTOK 785
#define D_  768
#define HH  28
#define PATCH 84
#define GCNH 512

#define ROWF4    192u          /* 768 floats per row */
#define BATF4    150720u       /* 785*192 per batch  */
#define NHS4     1205760u      /* 8*785*192          */
#define NCHUNK   588u          /* (8*784*192)/2048   */
#define KB_GRID  252u

// ---------------- scratch (no allocation allowed) ----------------
// amap/selflag layout: [b][s][c], c fastest
__device__ float         g_amap[B_*S_*C_];
__device__ unsigned char g_selflag[B_*S_*C_];
__device__ float         g_wk[B_*GCNH];
__device__ int           g_pidx[B_*S_];
__device__ int           g_key[B_*S_];

// ---------------- software grid barrier (KB only, 252 blocks) ----------------
__device__ unsigned g_gen = 0;
__device__ unsigned g_cnt = 0;

__device__ __forceinline__ void gridSync(unsigned nblk) {
    __syncthreads();
    if (threadIdx.x == 0) {
        volatile unsigned* vgen = &g_gen;
        unsigned my_gen = *vgen;                 // read gen BEFORE arriving
        __threadfence();                         // release prior writes
        if (atomicAdd(&g_cnt, 1u) == nblk - 1u) {
            g_cnt = 0;
            __threadfence();
            *vgen = my_gen + 1u;                 // release
        } else {
            while (*vgen == my_gen) { __nanosleep(32); }
        }
        __threadfence();                         // acquire
    }
    __syncthreads();
}

// monotone float->uint: a > b <=> f2u(a) > f2u(b)
__device__ __forceinline__ unsigned f2u(float f) {
    unsigned u = __float_as_uint(f);
    return (u & 0x80000000u) ? ~u : (u | 0x80000000u);
}

// ---- bulk copy of rows 1..784 (chunk = 2048 float4, ILP=8) ------------------
__device__ __forceinline__ void copy8(const float4* __restrict__ in4,
                                      float4* __restrict__ out4, unsigned chunk) {
    unsigned m0 = chunk * 2048u + threadIdx.x;
    unsigned src[8]; float4 v[8];
    #pragma unroll
    for (int e = 0; e < 8; e++) {
        unsigned m = m0 + (unsigned)e * 256u;       // m in [0, 8*784*192)
        unsigned b = m / 150528u;                   // 784*192 per batch
        src[e] = m + (b + 1u) * ROWF4;              // skip row 0 of each batch
    }
    #pragma unroll
    for (int e = 0; e < 8; e++) v[e] = in4[src[e]];
    #pragma unroll
    for (int e = 0; e < 8; e++) out4[src[e]] = v[e];
}

// ============ KA: 96 radix selects (0..95) + full copy (96..683) =============
__global__ void __launch_bounds__(256) KA(const float* __restrict__ x,
                                          const float4* __restrict__ in4,
                                          float4* __restrict__ out4) {
    if (blockIdx.x >= 96u) {
        copy8(in4, out4, blockIdx.x - 96u);        // chunks 0..587
        return;
    }
    int bc = blockIdx.x;
    int t  = threadIdx.x;
    unsigned lane = t & 31;
    int wid = t >> 5;
    __shared__ float    sc[S_];
    __shared__ unsigned key[S_];
    __shared__ int      hist[256];
    __shared__ int      wtot[8];
    __shared__ unsigned s_prefix;
    __shared__ int      s_k;

    const float* base = x + (size_t)bc * NTOK * NTOK + 1;   // x[b,c,0,1:]
    for (int s = t; s < S_; s += 256) {
        float v = base[s];
        sc[s]  = v;
        key[s] = f2u(v);
    }
    if (t == 0) { s_prefix = 0u; s_k = PATCH; }

    #pragma unroll
    for (int p = 0; p < 4; p++) {
        int shift = 24 - 8 * p;
        hist[t] = 0;
        __syncthreads();                           // publishes s_prefix/s_k too
        unsigned pref = s_prefix;
        int      k    = s_k;
        for (int s = t; s < S_; s += 256) {
            unsigned kk = key[s];
            bool cand = (p == 0) || (((kk ^ pref) >> (shift + 8)) == 0u);
            if (cand) atomicAdd(&hist[(kk >> shift) & 255], 1);
        }
        __syncthreads();
        int v = hist[t];
        int xsum = v;
        #pragma unroll
        for (int off = 1; off < 32; off <<= 1) {
            int y = __shfl_down_sync(0xFFFFFFFFu, xsum, off);
            if (lane + off < 32) xsum += y;
        }
        if (lane == 0) wtot[wid] = xsum;
        __syncthreads();
        int addhi = 0;
        for (int ww = wid + 1; ww < 8; ww++) addhi += wtot[ww];
        int suffix = xsum + addhi;                 // # candidates with bin >= t
        int above  = suffix - v;                   // # candidates with bin >  t
        if (suffix >= k && above < k) {            // exactly one thread matches
            s_prefix = pref | ((unsigned)t << shift);
            s_k      = k - above;
        }
    }
    __syncthreads();

    unsigned T  = s_prefix;
    int     neq = s_k;
    int b = bc / C_, c = bc - b * C_;
    unsigned baseo = (unsigned)(b * S_) * (unsigned)C_ + (unsigned)c;
    for (int s = t; s < S_; s += 256) {
        unsigned kk = key[s];
        bool sel;
        if (kk > T) sel = true;
        else if (kk == T) {
            int eq = 0;
            for (int u = 0; u < s; u++) eq += (key[u] == T);
            sel = eq < neq;
        } else sel = false;
        float v = sc[s];
        g_amap[baseo + (unsigned)s * C_]    = sel ? v : 0.7f * v;
        g_selflag[baseo + (unsigned)s * C_] = sel ? 1 : 0;
    }
}

// ---- per-batch analytics (rank-1 GCN collapse), blocks 0..7 of KB -----------
__device__ void doKB(const float* __restrict__ w1, int b,
                     float* pw, float* binm, float* cnt) {
    int t = threadIdx.x;
    unsigned lane = t & 31;
    int wid = t >> 5;
    const int NT = 256;
    __shared__ float  wsum[8];
    __shared__ unsigned long long wkey[8];
    __shared__ float4 wq[8];
    __shared__ float  s_mean, s_panchor;
    __shared__ float4 s_q;
    __shared__ int    s_anchor;

    const float4* ab4 = (const float4*)(g_amap + (size_t)b * S_ * C_);
    float part = 0.f;
    for (int s = t; s < S_; s += NT) {
        float4 a0 = ab4[s*3], a1 = ab4[s*3+1], a2 = ab4[s*3+2];
        float smv = a0.x+a0.y+a0.z+a0.w + a1.x+a1.y+a1.z+a1.w + a2.x+a2.y+a2.z+a2.w;
        binm[s] = smv;
        pw[s]   = smv * (1.f/12.f);
        part += smv;
    }
    #pragma unroll
    for (int off = 16; off > 0; off >>= 1) part += __shfl_down_sync(0xFFFFFFFFu, part, off);
    if (lane == 0) wsum[wid] = part;
    __syncthreads();
    if (t < 8) {
        float v = wsum[t];
        #pragma unroll
        for (int off = 4; off > 0; off >>= 1) v += __shfl_down_sync(0xFFu, v, off);
        if (t == 0) s_mean = v / (float)S_;
    }
    __syncthreads();
    float mean = s_mean;
    for (int s = t; s < S_; s += NT) binm[s] = (binm[s] > mean) ? 1.f : 0.f;

    unsigned long long akey = 0ull;
    for (int s = t; s < S_; s += NT) {
        float v = binm[s] * pw[s];
        unsigned uv = __float_as_uint(v);
        if (uv == 0x80000000u) uv = 0u;            // canonicalize -0.0
        unsigned fv = (uv & 0x80000000u) ? ~uv : (uv | 0x80000000u);
        unsigned long long k = ((unsigned long long)fv << 32) | (unsigned long long)(0xFFFFFFFFu - (unsigned)s);
        if (k > akey) akey = k;
    }
    #pragma unroll
    for (int off = 16; off > 0; off >>= 1) {
        unsigned long long o = __shfl_down_sync(0xFFFFFFFFu, akey, off);
        if (o > akey) akey = o;
    }
    if (lane == 0) wkey[wid] = akey;
    __syncthreads();
    if (t < 8) {
        unsigned long long k = wkey[t];
        #pragma unroll
        for (int off = 4; off > 0; off >>= 1) {
            unsigned long long o = __shfl_down_sync(0xFFu, k, off);
            if (o > k) k = o;
        }
        if (t == 0) {
            int a = (int)(0xFFFFFFFFu - (unsigned)(k & 0xFFFFFFFFull));
            s_anchor = a;
            s_panchor = pw[a];
        }
    }
    __syncthreads();
    int anchor = s_anchor;
    float ai = (float)(anchor / HH), aj = (float)(anchor % HH);

    float4 acc4 = make_float4(0.f, 0.f, 0.f, 0.f);
    for (int s = t; s < S_; s += NT) {
        float rx = ((float)(s / HH) - ai) / 28.0f;
        float ry = ((float)(s % HH) - aj) / 28.0f;
        float dist = sqrtf(rx*rx + ry*ry);
        float ang  = (atan2f(ry, rx) / (float)M_PI + 1.f) * 0.5f;
        float p = pw[s];
        acc4.x += p * dist;
        acc4.y += p * ang;
        if (p > 0.f) acc4.z += p*p; else if (p < 0.f) acc4.w += p*p;
    }
    #pragma unroll
    for (int off = 16; off > 0; off >>= 1) {
        acc4.x += __shfl_down_sync(0xFFFFFFFFu, acc4.x, off);
        acc4.y += __shfl_down_sync(0xFFFFFFFFu, acc4.y, off);
        acc4.z += __shfl_down_sync(0xFFFFFFFFu, acc4.z, off);
        acc4.w += __shfl_down_sync(0xFFFFFFFFu, acc4.w, off);
    }
    if (lane == 0) wq[wid] = acc4;
    __syncthreads();
    if (t < 8) {
        float4 a = wq[t];
        #pragma unroll
        for (int off = 4; off > 0; off >>= 1) {
            a.x += __shfl_down_sync(0xFFu, a.x, off);
            a.y += __shfl_down_sync(0xFFu, a.y, off);
            a.z += __shfl_down_sync(0xFFu, a.z, off);
            a.w += __shfl_down_sync(0xFFu, a.w, off);
        }
        if (t == 0) s_q = a;
    }
    __syncthreads();
    float Q0 = s_q.x, Q1 = s_q.y, AP = s_q.z, AM = s_q.w;
    float pa = s_panchor;

    for (int k = t; k < GCNH; k += NT) {
        float v = Q0 * w1[k] + Q1 * w1[GCNH + k];
        float wv = (v > 0.f) ? v * AP : ((v < 0.f) ? v * AM : 0.f);
        g_wk[b*GCNH + k] = pa * wv;
    }

    const unsigned* sf = (const unsigned*)(g_selflag + (size_t)b * S_ * C_);
    for (int s = t; s < S_; s += NT) {
        int acc = __dp4a((int)sf[s*3+2], 0x01010101,
                  __dp4a((int)sf[s*3+1], 0x01010101,
                  __dp4a((int)sf[s*3+0], 0x01010101, 0)));
        cnt[s] = (float)acc;
    }
    __syncthreads();
    for (int s = t; s < S_; s += NT) {
        int li = s / HH, lj = s % HH;
        float acc = 0.f;
        #pragma unroll
        for (int di = -1; di <= 1; di++) {
            #pragma unroll
            for (int dj = -1; dj <= 1; dj++) {
                int ni = li + di, nj = lj + dj;
                if (ni >= 0 && ni < HH && nj >= 0 && nj < HH) {
                    float kw = ((di == 0) ? 2.f : 1.f) * ((dj == 0) ? 2.f : 1.f);
                    acc += kw * cnt[ni*HH + nj];
                }
            }
        }
        g_key[b*S_ + s] = (int)acc * 1024 + (1023 - s);
    }
}

// ===== KB: analytics -> barrier -> matvec+rank -> barrier -> gather ==========
struct SmemKB  { float pw[S_]; float binm[S_]; float cnt[S_]; };
struct SmemMV  { float wk[GCNH]; float partr[256]; };
struct SmemRk  { int kk[S_]; };
union  SmemU   { SmemKB kb; SmemMV mv; SmemRk rk; };

__global__ void __launch_bounds__(256, 2)
KB(const float* __restrict__ w1, const float* __restrict__ w2,
   const float* __restrict__ hsf, float* __restrict__ outf,
   const float4* __restrict__ in4, float4* __restrict__ out4, unsigned sn) {
    __shared__ SmemU sm;
    unsigned bid = blockIdx.x;
    unsigned NB  = gridDim.x;
    int t = threadIdx.x;

    // Phase 1: per-batch analytics (blocks 0..7)
    if (bid < 8u) doKB(w1, (int)bid, sm.kb.pw, sm.kb.binm, sm.kb.cnt);
    gridSync(NB);

    // Phase 2: matvec + row0 write (0..191), rank (192..223)
    if (bid < 192u) {
        int b    = (int)(bid / 24u);
        int tile = (int)(bid - (unsigned)b * 24u);
        for (int k = t; k < GCNH; k += 256) sm.mv.wk[k] = g_wk[b*GCNH + k];
        __syncthreads();
        int col = tile * 32 + (t & 31);
        int jq  = t >> 5;
        const float* w2p = w2 + col;
        float acc = 0.f;
        int j0 = jq * 64;
        #pragma unroll 8
        for (int j = 0; j < 64; j++) acc += sm.mv.wk[j0 + j] * w2p[(size_t)(j0 + j) * D_];
        sm.mv.partr[t] = acc;
        __syncthreads();
        if (t < 32) {
            float o = 0.f;
            #pragma unroll
            for (int q = 0; q < 8; q++) o += sm.mv.partr[t + q*32];
            int c = tile * 32 + t;
            float st = (o > 0.f) ? o : 0.2f * o;
            unsigned idx = (unsigned)b * 602880u + (unsigned)c;   // row 0 of batch b
            outf[idx] = hsf[idx] + st;
        }
    } else if (bid < 224u) {
        unsigned idx = bid - 192u;                 // 0..31
        int b    = (int)(idx >> 2);
        int part = (int)(idx & 3u);
        for (int s = t; s < S_; s += 256) sm.rk.kk[s] = g_key[b*S_ + s];
        __syncthreads();
        if (t < 196) {
            int s = part * 196 + t;
            int ks = sm.rk.kk[s];
            int r = 0;
            #pragma unroll 8
            for (int u = 0; u < S_; u++) r += (sm.rk.kk[u] > ks);
            if (r < (int)sn) g_pidx[b*S_ + r] = s + 1;
        }
    }
    gridSync(NB);

    // Phase 3: gather selected rows (grid-stride; at sn=42 exactly 1 elem/thread)
    unsigned ng = sn * 8u * ROWF4;
    for (unsigned j = bid * 256u + (unsigned)t; j < ng; j += NB * 256u) {
        unsigned rr = j / ROWF4;                   // b*sn + jj
        unsigned k4 = j - rr * ROWF4;
        unsigned b  = rr / sn;
        unsigned jj = rr - b * sn;
        unsigned row = (unsigned)g_pidx[b*S_ + jj];
        out4[NHS4 + j] = in4[(b*785u + row)*ROWF4 + k4];
    }
}

// ---------------- launch ----------------
extern "C" void kernel_launch(void* const* d_in, const int* in_sizes, int n_in,
                              void* d_out, int out_size) {
    const float* hs = (const float*)d_in[0];
    const float* x  = (const float*)d_in[1];
    const float* w1 = (const float*)d_in[2];
    const float* w2 = (const float*)d_in[3];
    (void)in_sizes; (void)n_in;

    int sn = out_size / (B_ * D_) - NTOK;          // selected rows per batch
    if (sn < 1) sn = 1;
    if (sn > S_) sn = S_;

    const float4* in4 = (const float4*)hs;
    float4* out4 = (float4*)d_out;

    KA<<<96u + NCHUNK, 256>>>(x, in4, out4);
    KB<<<KB_GRID, 256>>>(w1, w2, hs, (float*)d_out, in4, out4, (unsigned)sn);
}